// round 4
// baseline (speedup 1.0000x reference)
#include <cuda_runtime.h>

#define Bdim 8
#define Ndim 8
#define Tdim 262144
#define ROWS (Bdim * Ndim)              // 64
#define CHUNKS 16                       // chunks per eIF row
#define EIF_ITEMS (ROWS * CHUNKS)       // 1024
#define RECON_ITEMS 256
#define TOTAL_ITEMS (EIF_ITEMS + RECON_ITEMS)   // 1280
#define THREADS 256
#define NBLOCKS (148 * 7)               // persistent single wave @ 7 blocks/SM
#define VEC_PER_CHUNK (Tdim / CHUNKS / 4)           // 4096 float4 per eIF chunk
#define EIF_ITERS (VEC_PER_CHUNK / THREADS)         // 16
#define RECON_VEC_PER_ITEM 2048         // float4 per recon item (per array)
#define RECON_ITERS (RECON_VEC_PER_ITEM / THREADS)  // 8

// [0]=recon_sum, [1]=if_sum, [2]=smooth_sum. Zero at module load; the
// last-finishing block resets all state after reading, so every
// kernel_launch (correctness, capture, every replay) starts from zero.
__device__ double g_acc[3];
__device__ unsigned int g_item;   // dynamic work ticket
__device__ unsigned int g_done;   // completion counter

__device__ __forceinline__ float block_reduce(float v, float* sm) {
    #pragma unroll
    for (int o = 16; o > 0; o >>= 1) v += __shfl_down_sync(0xffffffffu, v, o);
    int warp = threadIdx.x >> 5;
    __syncthreads();
    if ((threadIdx.x & 31) == 0) sm[warp] = v;
    __syncthreads();
    if (warp == 0) {
        v = (threadIdx.x < (THREADS >> 5)) ? sm[threadIdx.x] : 0.0f;
        #pragma unroll
        for (int o = 4; o > 0; o >>= 1) v += __shfl_down_sync(0xffffffffu, v, o);
    }
    return v;
}

__global__ void __launch_bounds__(THREADS, 7)
loss_fused_kernel(const float* __restrict__ rr, const float* __restrict__ ri,
                  const float* __restrict__ tr, const float* __restrict__ ti,
                  const float* __restrict__ eIF, const float* __restrict__ tif,
                  const int* __restrict__ mode_mask, float* __restrict__ out)
{
    __shared__ float sm[THREADS / 32];
    __shared__ int sh_item;
    const int tid = threadIdx.x;

    float acc_rec = 0.0f, acc_if = 0.0f, acc_sm = 0.0f;

    for (;;) {
        if (tid == 0) sh_item = (int)atomicAdd(&g_item, 1u);
        __syncthreads();
        const int item = sh_item;
        __syncthreads();              // sh_item safe to overwrite next iter
        if (item >= TOTAL_ITEMS) break;

        if (item < EIF_ITEMS) {
            // ---- eIF / target_if: one (row, chunk) per item ----
            const int row = item >> 4;
            if (mode_mask[row] != 1) continue;   // uniform branch; zero traffic
            const int chunk = item & 15;

            const size_t row_off = (size_t)row * Tdim;
            const float4* __restrict__ e4 = (const float4*)(eIF + row_off);
            const float4* __restrict__ t4 = (const float4*)(tif + row_off);
            const float*  __restrict__ er = eIF + row_off;

            const int vbase = chunk * VEC_PER_CHUNK;

            #pragma unroll 4
            for (int i = 0; i < EIF_ITERS; i++) {
                const int v = vbase + i * THREADS + tid;
                const float4 e  = e4[v];
                const float4 tf = t4[v];

                float dx = e.x - tf.x, dy = e.y - tf.y, dz = e.z - tf.z, dw = e.w - tf.w;
                acc_if += dx * dx + dy * dy + dz * dz + dw * dw;

                float d1 = e.y - e.x, d2 = e.z - e.y, d3 = e.w - e.z;
                acc_sm += d1 * d1 + d2 * d2 + d3 * d3;

                // neighbor e[t+4]: next lane's e.x, scalar patch at warp edge
                const int t = v * 4;
                float nx = __shfl_down_sync(0xffffffffu, e.x, 1);
                if ((tid & 31) == 31 && (t + 4 < Tdim)) nx = er[t + 4];
                if (t + 4 < Tdim) { float d4 = nx - e.w; acc_sm += d4 * d4; }
            }
        } else {
            // ---- recon: contiguous 2048-float4 slab per item, 4 arrays ----
            const int r = item - EIF_ITEMS;
            const int base = r * RECON_VEC_PER_ITEM;
            const float4* __restrict__ a = (const float4*)rr;
            const float4* __restrict__ b = (const float4*)ri;
            const float4* __restrict__ c = (const float4*)tr;
            const float4* __restrict__ d = (const float4*)ti;

            #pragma unroll
            for (int j = 0; j < RECON_ITERS; j++) {
                const int v = base + j * THREADS + tid;
                const float4 xr = a[v], xt = c[v];
                const float4 yr = b[v], yt = d[v];
                float d0 = xr.x - xt.x, d1 = xr.y - xt.y, d2 = xr.z - xt.z, d3 = xr.w - xt.w;
                acc_rec += d0 * d0 + d1 * d1 + d2 * d2 + d3 * d3;
                float e0 = yr.x - yt.x, e1 = yr.y - yt.y, e2 = yr.z - yt.z, e3 = yr.w - yt.w;
                acc_rec += e0 * e0 + e1 * e1 + e2 * e2 + e3 * e3;
            }
        }
    }

    // one reduction + 3 double atomics per block
    acc_rec = block_reduce(acc_rec, sm);
    acc_if  = block_reduce(acc_if,  sm);
    acc_sm  = block_reduce(acc_sm,  sm);

    if (tid == 0) {
        atomicAdd(&g_acc[0], (double)acc_rec);
        atomicAdd(&g_acc[1], (double)acc_if);
        atomicAdd(&g_acc[2], (double)acc_sm);
        __threadfence();
        unsigned int prev = atomicAdd(&g_done, 1u);
        if (prev == (unsigned int)(gridDim.x - 1)) {
            double s_recon  = atomicAdd(&g_acc[0], 0.0);
            double s_if     = atomicAdd(&g_acc[1], 0.0);
            double s_smooth = atomicAdd(&g_acc[2], 0.0);

            float count = 0.0f;
            #pragma unroll
            for (int i = 0; i < ROWS; i++) count += (mode_mask[i] == 1) ? 1.0f : 0.0f;

            const double recon  = s_recon  / ((double)Bdim * (double)Tdim);
            const double ifl    = s_if     / ((double)Bdim * (double)Ndim * (double)Tdim);
            const double smooth = (s_smooth / (double)(Tdim - 1)) / (double)fmaxf(count, 1.0f);
            const double total  = recon + 0.5 * ifl + ((count > 0.0f) ? 0.1 * smooth : 0.0);

            out[0] = (float)total;
            out[1] = (float)recon;
            out[2] = (float)ifl;
            out[3] = (float)smooth;

            // reset ALL device state for the next graph replay
            g_acc[0] = 0.0; g_acc[1] = 0.0; g_acc[2] = 0.0;
            g_item = 0u;
            __threadfence();
            g_done = 0u;
        }
    }
}

extern "C" void kernel_launch(void* const* d_in, const int* in_sizes, int n_in,
                              void* d_out, int out_size)
{
    const float* recon_real  = (const float*)d_in[0];
    const float* recon_imag  = (const float*)d_in[1];
    const float* target_real = (const float*)d_in[2];
    const float* target_imag = (const float*)d_in[3];
    const float* eIF         = (const float*)d_in[4];
    const float* target_if   = (const float*)d_in[5];
    const int*   mode_mask   = (const int*)d_in[6];
    float* out = (float*)d_out;

    loss_fused_kernel<<<NBLOCKS, THREADS>>>(
        recon_real, recon_imag, target_real, target_imag, eIF, target_if,
        mode_mask, out);
}

// round 5
// speedup vs baseline: 1.4485x; 1.4485x over previous
#include <cuda_runtime.h>

#define Bdim 8
#define Ndim 8
#define Tdim 262144
#define ROWS (Bdim * Ndim)            // 64
#define CHUNKS 16                     // chunks per eIF row
#define EIF_BLOCKS (ROWS * CHUNKS)    // 1024
#define RECON_BLOCKS 256
#define THREADS 256
#define VEC_PER_CHUNK (Tdim / CHUNKS / 4)          // 4096 float4 per chunk
#define EIF_ITERS (VEC_PER_CHUNK / THREADS)        // 16
#define RECON_VEC (Bdim * Tdim / 4)                // 524288 float4 per array
#define RECON_ITERS (RECON_VEC / (RECON_BLOCKS * THREADS))  // 8

// accumulators: [0]=recon_sum, [1]=if_sum, [2]=smooth_sum (mask-weighted).
// Zero-initialized at module load; finalize_kernel resets them after each
// read so every kernel_launch call (correctness, capture, replays) starts
// from zero.
__device__ double g_acc[3];

__device__ __forceinline__ float block_reduce(float v, float* sm) {
    #pragma unroll
    for (int o = 16; o > 0; o >>= 1) v += __shfl_down_sync(0xffffffffu, v, o);
    int warp = threadIdx.x >> 5;
    __syncthreads();                 // protect sm from any previous use
    if ((threadIdx.x & 31) == 0) sm[warp] = v;
    __syncthreads();
    if (warp == 0) {
        v = (threadIdx.x < (THREADS >> 5)) ? sm[threadIdx.x] : 0.0f;
        #pragma unroll
        for (int o = 4; o > 0; o >>= 1) v += __shfl_down_sync(0xffffffffu, v, o);
    }
    return v;
}

__global__ void __launch_bounds__(THREADS)
loss_main_kernel(const float* __restrict__ rr, const float* __restrict__ ri,
                 const float* __restrict__ tr, const float* __restrict__ ti,
                 const float* __restrict__ eIF, const float* __restrict__ tif,
                 const int* __restrict__ mode_mask)
{
    __shared__ float sm[THREADS / 32];
    const int tid = threadIdx.x;
    const int bid = blockIdx.x;

    if (bid < EIF_BLOCKS) {
        // ---- eIF / target_if path: one (row, chunk) per block ----
        const int row   = bid / CHUNKS;
        const int chunk = bid % CHUNKS;
        if (mode_mask[row] != 1) return;   // masked row contributes NOTHING: skip all traffic

        const size_t row_off = (size_t)row * Tdim;
        const float4* __restrict__ e4 = (const float4*)(eIF + row_off);
        const float4* __restrict__ t4 = (const float4*)(tif + row_off);
        const float*  __restrict__ er = eIF + row_off;

        const int vbase = chunk * VEC_PER_CHUNK;
        float acc_if = 0.0f, acc_sm = 0.0f;

        #pragma unroll 4
        for (int i = 0; i < EIF_ITERS; i++) {
            const int v = vbase + i * THREADS + tid;
            const float4 e  = e4[v];
            const float4 tf = t4[v];

            float dx = e.x - tf.x, dy = e.y - tf.y, dz = e.z - tf.z, dw = e.w - tf.w;
            acc_if += dx * dx + dy * dy + dz * dz + dw * dw;

            float d1 = e.y - e.x, d2 = e.z - e.y, d3 = e.w - e.z;
            acc_sm += d1 * d1 + d2 * d2 + d3 * d3;

            // neighbor element e[t+4]: next lane's e.x, or scalar load at warp edge
            const int t = v * 4;
            float nx = __shfl_down_sync(0xffffffffu, e.x, 1);
            if ((tid & 31) == 31 && (t + 4 < Tdim)) nx = er[t + 4];
            if (t + 4 < Tdim) { float d4 = nx - e.w; acc_sm += d4 * d4; }
        }

        acc_if = block_reduce(acc_if, sm);
        acc_sm = block_reduce(acc_sm, sm);
        if (tid == 0) {
            atomicAdd(&g_acc[1], (double)acc_if);
            atomicAdd(&g_acc[2], (double)acc_sm);
        }
    } else {
        // ---- recon path: grid-stride over B*T with float4 ----
        const int rb = bid - EIF_BLOCKS;
        const float4* __restrict__ a = (const float4*)rr;
        const float4* __restrict__ b = (const float4*)ri;
        const float4* __restrict__ c = (const float4*)tr;
        const float4* __restrict__ d = (const float4*)ti;

        float acc = 0.0f;
        #pragma unroll
        for (int j = 0; j < RECON_ITERS; j++) {
            const int v = rb * THREADS + tid + j * (RECON_BLOCKS * THREADS);
            const float4 xr = a[v], xt = c[v];
            const float4 yr = b[v], yt = d[v];
            float d0 = xr.x - xt.x, d1 = xr.y - xt.y, d2 = xr.z - xt.z, d3 = xr.w - xt.w;
            acc += d0 * d0 + d1 * d1 + d2 * d2 + d3 * d3;
            float e0 = yr.x - yt.x, e1 = yr.y - yt.y, e2 = yr.z - yt.z, e3 = yr.w - yt.w;
            acc += e0 * e0 + e1 * e1 + e2 * e2 + e3 * e3;
        }
        acc = block_reduce(acc, sm);
        if (tid == 0) atomicAdd(&g_acc[0], (double)acc);
    }
}

// One warp: parallel mask count (32 lanes x 2 entries), lane 0 does the math.
__global__ void finalize_kernel(const int* __restrict__ mode_mask, float* __restrict__ out) {
    const int lid = threadIdx.x;   // 0..31

    int m = (mode_mask[lid] == 1) + (mode_mask[lid + 32] == 1);
    #pragma unroll
    for (int o = 16; o > 0; o >>= 1) m += __shfl_down_sync(0xffffffffu, m, o);

    if (lid == 0) {
        const float count = (float)m;
        // plain loads: ordered by kernel boundary after loss_main_kernel
        const double s_recon  = g_acc[0];
        const double s_if     = g_acc[1];
        const double s_smooth = g_acc[2];

        const double recon  = s_recon  / ((double)Bdim * (double)Tdim);
        const double ifl    = s_if     / ((double)Bdim * (double)Ndim * (double)Tdim);
        const double smooth = (s_smooth / (double)(Tdim - 1)) / (double)fmaxf(count, 1.0f);
        const double total  = recon + 0.5 * ifl + ((count > 0.0f) ? 0.1 * smooth : 0.0);

        out[0] = (float)total;
        out[1] = (float)recon;
        out[2] = (float)ifl;
        out[3] = (float)smooth;

        // Reset accumulators so the next kernel_launch call starts from zero.
        g_acc[0] = 0.0; g_acc[1] = 0.0; g_acc[2] = 0.0;
    }
}

extern "C" void kernel_launch(void* const* d_in, const int* in_sizes, int n_in,
                              void* d_out, int out_size)
{
    const float* recon_real  = (const float*)d_in[0];
    const float* recon_imag  = (const float*)d_in[1];
    const float* target_real = (const float*)d_in[2];
    const float* target_imag = (const float*)d_in[3];
    const float* eIF         = (const float*)d_in[4];
    const float* target_if   = (const float*)d_in[5];
    const int*   mode_mask   = (const int*)d_in[6];
    float* out = (float*)d_out;

    loss_main_kernel<<<EIF_BLOCKS + RECON_BLOCKS, THREADS>>>(
        recon_real, recon_imag, target_real, target_imag, eIF, target_if, mode_mask);
    finalize_kernel<<<1, 32>>>(mode_mask, out);
}

// round 6
// speedup vs baseline: 1.4610x; 1.0087x over previous
#include <cuda_runtime.h>

#define Bdim 8
#define Ndim 8
#define Tdim 262144
#define ROWS (Bdim * Ndim)            // 64
#define CHUNKS 16                     // chunks per eIF row
#define EIF_BLOCKS (ROWS * CHUNKS)    // 1024
#define RECON_BLOCKS 256
#define THREADS 256
#define VEC_PER_CHUNK (Tdim / CHUNKS / 4)          // 4096 float4 per chunk
#define EIF_ITERS (VEC_PER_CHUNK / THREADS)        // 16
#define RECON_VEC (Bdim * Tdim / 4)                // 524288 float4 per array
#define RECON_ITERS (RECON_VEC / (RECON_BLOCKS * THREADS))  // 8

// accumulators: [0]=recon_sum, [1]=if_sum, [2]=smooth_sum (mask-weighted).
// Zero-initialized at module load; finalize_kernel resets them after each
// read so every kernel_launch call (correctness, capture, replays) starts
// from zero.
__device__ double g_acc[3];

__device__ __forceinline__ void pdl_launch_dependents() {
    asm volatile("griddepcontrol.launch_dependents;" ::: "memory");
}
__device__ __forceinline__ void pdl_wait() {
    asm volatile("griddepcontrol.wait;" ::: "memory");
}

__device__ __forceinline__ float block_reduce(float v, float* sm) {
    #pragma unroll
    for (int o = 16; o > 0; o >>= 1) v += __shfl_down_sync(0xffffffffu, v, o);
    int warp = threadIdx.x >> 5;
    __syncthreads();                 // protect sm from any previous use
    if ((threadIdx.x & 31) == 0) sm[warp] = v;
    __syncthreads();
    if (warp == 0) {
        v = (threadIdx.x < (THREADS >> 5)) ? sm[threadIdx.x] : 0.0f;
        #pragma unroll
        for (int o = 4; o > 0; o >>= 1) v += __shfl_down_sync(0xffffffffu, v, o);
    }
    return v;
}

__global__ void __launch_bounds__(THREADS)
loss_main_kernel(const float* __restrict__ rr, const float* __restrict__ ri,
                 const float* __restrict__ tr, const float* __restrict__ ti,
                 const float* __restrict__ eIF, const float* __restrict__ tif,
                 const int* __restrict__ mode_mask)
{
    __shared__ float sm[THREADS / 32];
    const int tid = threadIdx.x;
    const int bid = blockIdx.x;

    // Allow the finalize kernel to launch early; correctness is enforced by
    // its griddepcontrol.wait (which waits for THIS grid's memory to land).
    pdl_launch_dependents();

    if (bid < EIF_BLOCKS) {
        // ---- eIF / target_if path: one (row, chunk) per block ----
        const int row   = bid / CHUNKS;
        const int chunk = bid % CHUNKS;
        if (mode_mask[row] != 1) return;   // masked row contributes NOTHING: skip all traffic

        const size_t row_off = (size_t)row * Tdim;
        const float4* __restrict__ e4 = (const float4*)(eIF + row_off);
        const float4* __restrict__ t4 = (const float4*)(tif + row_off);
        const float*  __restrict__ er = eIF + row_off;

        const int vbase = chunk * VEC_PER_CHUNK;
        float acc_if = 0.0f, acc_sm = 0.0f;

        #pragma unroll 4
        for (int i = 0; i < EIF_ITERS; i++) {
            const int v = vbase + i * THREADS + tid;
            const float4 e  = e4[v];
            const float4 tf = t4[v];

            float dx = e.x - tf.x, dy = e.y - tf.y, dz = e.z - tf.z, dw = e.w - tf.w;
            acc_if += dx * dx + dy * dy + dz * dz + dw * dw;

            float d1 = e.y - e.x, d2 = e.z - e.y, d3 = e.w - e.z;
            acc_sm += d1 * d1 + d2 * d2 + d3 * d3;

            // neighbor element e[t+4]: next lane's e.x, or scalar load at warp edge
            const int t = v * 4;
            float nx = __shfl_down_sync(0xffffffffu, e.x, 1);
            if ((tid & 31) == 31 && (t + 4 < Tdim)) nx = er[t + 4];
            if (t + 4 < Tdim) { float d4 = nx - e.w; acc_sm += d4 * d4; }
        }

        acc_if = block_reduce(acc_if, sm);
        acc_sm = block_reduce(acc_sm, sm);
        if (tid == 0) {
            atomicAdd(&g_acc[1], (double)acc_if);
            atomicAdd(&g_acc[2], (double)acc_sm);
        }
    } else {
        // ---- recon path: grid-stride over B*T with float4 ----
        const int rb = bid - EIF_BLOCKS;
        const float4* __restrict__ a = (const float4*)rr;
        const float4* __restrict__ b = (const float4*)ri;
        const float4* __restrict__ c = (const float4*)tr;
        const float4* __restrict__ d = (const float4*)ti;

        float acc = 0.0f;
        #pragma unroll
        for (int j = 0; j < RECON_ITERS; j++) {
            const int v = rb * THREADS + tid + j * (RECON_BLOCKS * THREADS);
            const float4 xr = a[v], xt = c[v];
            const float4 yr = b[v], yt = d[v];
            float d0 = xr.x - xt.x, d1 = xr.y - xt.y, d2 = xr.z - xt.z, d3 = xr.w - xt.w;
            acc += d0 * d0 + d1 * d1 + d2 * d2 + d3 * d3;
            float e0 = yr.x - yt.x, e1 = yr.y - yt.y, e2 = yr.z - yt.z, e3 = yr.w - yt.w;
            acc += e0 * e0 + e1 * e1 + e2 * e2 + e3 * e3;
        }
        acc = block_reduce(acc, sm);
        if (tid == 0) atomicAdd(&g_acc[0], (double)acc);
    }
}

// One warp. Launched with PDL: prologue (mask count) overlaps the primary's
// tail; griddepcontrol.wait then orders the g_acc reads after the primary.
__global__ void finalize_kernel(const int* __restrict__ mode_mask, float* __restrict__ out) {
    const int lid = threadIdx.x;   // 0..31

    int m = (mode_mask[lid] == 1) + (mode_mask[lid + 32] == 1);
    #pragma unroll
    for (int o = 16; o > 0; o >>= 1) m += __shfl_down_sync(0xffffffffu, m, o);

    pdl_wait();   // primary grid complete; its atomics to g_acc visible

    if (lid == 0) {
        const float count = (float)m;
        const double s_recon  = g_acc[0];
        const double s_if     = g_acc[1];
        const double s_smooth = g_acc[2];

        const double recon  = s_recon  / ((double)Bdim * (double)Tdim);
        const double ifl    = s_if     / ((double)Bdim * (double)Ndim * (double)Tdim);
        const double smooth = (s_smooth / (double)(Tdim - 1)) / (double)fmaxf(count, 1.0f);
        const double total  = recon + 0.5 * ifl + ((count > 0.0f) ? 0.1 * smooth : 0.0);

        out[0] = (float)total;
        out[1] = (float)recon;
        out[2] = (float)ifl;
        out[3] = (float)smooth;

        // Reset accumulators so the next kernel_launch call starts from zero.
        g_acc[0] = 0.0; g_acc[1] = 0.0; g_acc[2] = 0.0;
    }
}

extern "C" void kernel_launch(void* const* d_in, const int* in_sizes, int n_in,
                              void* d_out, int out_size)
{
    const float* recon_real  = (const float*)d_in[0];
    const float* recon_imag  = (const float*)d_in[1];
    const float* target_real = (const float*)d_in[2];
    const float* target_imag = (const float*)d_in[3];
    const float* eIF         = (const float*)d_in[4];
    const float* target_if   = (const float*)d_in[5];
    const int*   mode_mask   = (const int*)d_in[6];
    float* out = (float*)d_out;

    loss_main_kernel<<<EIF_BLOCKS + RECON_BLOCKS, THREADS>>>(
        recon_real, recon_imag, target_real, target_imag, eIF, target_if, mode_mask);

    // Finalize with Programmatic Dependent Launch so its launch + prologue
    // overlap the primary's tail.
    cudaLaunchConfig_t cfg = {};
    cfg.gridDim  = dim3(1);
    cfg.blockDim = dim3(32);
    cfg.dynamicSmemBytes = 0;
    cfg.stream = 0;
    cudaLaunchAttribute attr[1];
    attr[0].id = cudaLaunchAttributeProgrammaticStreamSerialization;
    attr[0].val.programmaticStreamSerializationAllowed = 1;
    cfg.attrs = attr;
    cfg.numAttrs = 1;
    cudaLaunchKernelEx(&cfg, finalize_kernel, mode_mask, (float*)d_out);
}